// round 16
// baseline (speedup 1.0000x reference)
#include <cuda_runtime.h>
#include <cstdint>
#include <math.h>

#define PRE        128
#define NSTRIDE    384          // per-node row in P: [SL(128) | SR(128) | U(128)]
#define MAX_NODES  100000

// Scratch: per-node precomputed activations/transform. 100000*384*4 = 153.6 MB.
static __device__ __align__(16) float g_P[(size_t)MAX_NODES * NSTRIDE];

// edges-dtype flag: 1 if edges buffer is int32, 0 if int64.
static __device__ int g_is32;

__device__ __forceinline__ unsigned f2tf(float x) {
    unsigned u;
    asm("cvt.rna.tf32.f32 %0, %1;" : "=r"(u) : "f"(x));
    return u;
}

// ---------------------------------------------------------------------------
// Dtype detection: read the first n64 u64 words (= E words; in-bounds for both
// int32 [full buffer] and int64 [first half]). True int64 indices are all
// < 100000; int32 pairs fused into a u64 have the second index in the high
// bits -> astronomically large. Any value >= MAX_NODES => int32.
// ---------------------------------------------------------------------------
__global__ void reset_flag_kernel() { g_is32 = 0; }

__global__ void detect_kernel(const unsigned long long* __restrict__ p, int n64) {
    int i = blockIdx.x * blockDim.x + threadIdx.x;
    int stride = gridDim.x * blockDim.x;
    bool bad = false;
    for (; i < n64; i += stride)
        bad |= (p[i] >= (unsigned long long)MAX_NODES);
    if (bad) g_is32 = 1;
}

// ---------------------------------------------------------------------------
// Kernel 1: P[n] = [ sigmoid(emb[n]@Wl^T) | sigmoid(emb[n]@Wr^T) | emb[n]@Wu^T ]
// grid = (ceil(M/64), 3), block = 256 threads (8 warps, 2(M) x 4(N) layout)
// Block tile: 64 rows x 128 cols x K=128, tf32 mma.sync m16n8k8.
// ---------------------------------------------------------------------------
__global__ void node_gemm_kernel(const float* __restrict__ emb,
                                 const float* __restrict__ Wl,
                                 const float* __restrict__ Wr,
                                 const float* __restrict__ Wu,
                                 int M) {
    extern __shared__ float sm[];
    float* As = sm;                 // [64][132]
    float* Bs = sm + 64 * 132;      // [128][132]
    const int LD = 132;

    const int seg = blockIdx.y;     // 0 = SL, 1 = SR, 2 = U
    const float* W = (seg == 0) ? Wl : (seg == 1) ? Wr : Wu;
    const int m0 = blockIdx.x * 64;
    const int tid = threadIdx.x;

    // Stage B (weights, 128x128) as tf32-rounded floats: 4096 float4, 16/thread
#pragma unroll
    for (int i = 0; i < 16; i++) {
        int idx = tid + i * 256;
        int n = idx >> 5;
        int c4 = idx & 31;
        float4 v = __ldg((const float4*)(W + n * PRE) + c4);
        float* dst = &Bs[n * LD + c4 * 4];
        dst[0] = __uint_as_float(f2tf(v.x));
        dst[1] = __uint_as_float(f2tf(v.y));
        dst[2] = __uint_as_float(f2tf(v.z));
        dst[3] = __uint_as_float(f2tf(v.w));
    }
    // Stage A (64x128 node rows): 2048 float4, 8/thread, bounds-guarded
#pragma unroll
    for (int i = 0; i < 8; i++) {
        int idx = tid + i * 256;
        int r = idx >> 5;
        int c4 = idx & 31;
        float4 v = make_float4(0.f, 0.f, 0.f, 0.f);
        if (m0 + r < M)
            v = __ldg((const float4*)(emb + (size_t)(m0 + r) * PRE) + c4);
        float* dst = &As[r * LD + c4 * 4];
        dst[0] = __uint_as_float(f2tf(v.x));
        dst[1] = __uint_as_float(f2tf(v.y));
        dst[2] = __uint_as_float(f2tf(v.z));
        dst[3] = __uint_as_float(f2tf(v.w));
    }
    __syncthreads();

    const int lane = tid & 31;
    const int wid = tid >> 5;
    const int wm = wid & 1;         // warp row: 32 node-rows each
    const int wn = wid >> 1;        // warp col: 32 out-cols each
    const int g  = lane >> 2;       // groupID 0..7
    const int t4 = lane & 3;        // threadID_in_group 0..3

    float acc[2][4][4];
#pragma unroll
    for (int mi = 0; mi < 2; mi++)
#pragma unroll
        for (int ni = 0; ni < 4; ni++)
#pragma unroll
            for (int j = 0; j < 4; j++) acc[mi][ni][j] = 0.f;

#pragma unroll
    for (int ko = 0; ko < 16; ko++) {
        const int c0 = ko * 8 + t4;
        unsigned a[2][4];
#pragma unroll
        for (int mi = 0; mi < 2; mi++) {
            int r0 = wm * 32 + mi * 16 + g;
            a[mi][0] = __float_as_uint(As[r0 * LD + c0]);
            a[mi][1] = __float_as_uint(As[(r0 + 8) * LD + c0]);
            a[mi][2] = __float_as_uint(As[r0 * LD + c0 + 4]);
            a[mi][3] = __float_as_uint(As[(r0 + 8) * LD + c0 + 4]);
        }
#pragma unroll
        for (int ni = 0; ni < 4; ni++) {
            int nr = wn * 32 + ni * 8 + g;
            unsigned b0 = __float_as_uint(Bs[nr * LD + c0]);
            unsigned b1 = __float_as_uint(Bs[nr * LD + c0 + 4]);
#pragma unroll
            for (int mi = 0; mi < 2; mi++) {
                asm volatile(
                    "mma.sync.aligned.m16n8k8.row.col.f32.tf32.tf32.f32 "
                    "{%0,%1,%2,%3}, {%4,%5,%6,%7}, {%8,%9}, {%0,%1,%2,%3};\n"
                    : "+f"(acc[mi][ni][0]), "+f"(acc[mi][ni][1]),
                      "+f"(acc[mi][ni][2]), "+f"(acc[mi][ni][3])
                    : "r"(a[mi][0]), "r"(a[mi][1]), "r"(a[mi][2]), "r"(a[mi][3]),
                      "r"(b0), "r"(b1));
            }
        }
    }

    // Epilogue: sigmoid for segments 0/1, raw for U (bias+tanh happen per-edge)
#pragma unroll
    for (int mi = 0; mi < 2; mi++) {
#pragma unroll
        for (int ni = 0; ni < 4; ni++) {
            int row0 = m0 + wm * 32 + mi * 16 + g;
            int col = wn * 32 + ni * 8 + t4 * 2;
            float v0 = acc[mi][ni][0], v1 = acc[mi][ni][1];
            float v2 = acc[mi][ni][2], v3 = acc[mi][ni][3];
            if (seg < 2) {
                v0 = 1.f / (1.f + expf(-v0));
                v1 = 1.f / (1.f + expf(-v1));
                v2 = 1.f / (1.f + expf(-v2));
                v3 = 1.f / (1.f + expf(-v3));
            }
            if (row0 < M) {
                float2* p = (float2*)&g_P[(size_t)row0 * NSTRIDE + seg * 128 + col];
                *p = make_float2(v0, v1);
            }
            if (row0 + 8 < M) {
                float2* p = (float2*)&g_P[(size_t)(row0 + 8) * NSTRIDE + seg * 128 + col];
                *p = make_float2(v2, v3);
            }
        }
    }
}

// ---------------------------------------------------------------------------
// Kernel 2: per-edge gather + elementwise.
// 1 warp per edge, each lane owns 4 consecutive output columns (float4).
// out[e] = (SL[a] + SR[b]) * tanh(U[a] + U[b] + bias)
// ---------------------------------------------------------------------------
__global__ void edge_kernel(const void* __restrict__ edges,
                            const float* __restrict__ bias,
                            float* __restrict__ out,
                            int E, int M) {
    int w = (int)((blockIdx.x * blockDim.x + threadIdx.x) >> 5);
    if (w >= E) return;
    int lane = threadIdx.x & 31;

    long long ia, ib;
    if (g_is32) {
        int2 e = __ldg((const int2*)edges + w);
        ia = e.x; ib = e.y;
    } else {
        longlong2 e = __ldg((const longlong2*)edges + w);
        ia = e.x; ib = e.y;
    }
    // safety clamp (no-op for valid data)
    ia = (ia < 0) ? 0 : (ia >= M ? M - 1 : ia);
    ib = (ib < 0) ? 0 : (ib >= M ? M - 1 : ib);

    const float4* Pa = (const float4*)(g_P + (size_t)ia * NSTRIDE);
    const float4* Pb = (const float4*)(g_P + (size_t)ib * NSTRIDE);

    float4 sl = Pa[lane];           // SL[a], cols 4*lane..
    float4 sr = Pb[32 + lane];      // SR[b]
    float4 ua = Pa[64 + lane];      // U[a]
    float4 ub = Pb[64 + lane];      // U[b]
    float4 bv = __ldg((const float4*)bias + lane);

    float4 o;
    o.x = (sl.x + sr.x) * tanhf(ua.x + ub.x + bv.x);
    o.y = (sl.y + sr.y) * tanhf(ua.y + ub.y + bv.y);
    o.z = (sl.z + sr.z) * tanhf(ua.z + ub.z + bv.z);
    o.w = (sl.w + sr.w) * tanhf(ua.w + ub.w + bv.w);

    ((float4*)out)[(size_t)w * 32 + lane] = o;
}

// ---------------------------------------------------------------------------
// Inputs (metadata order): node_embedding f32 [100000*128],
// edges int32-or-int64 [600000*2] (dtype auto-detected),
// W_left f32 [128*128], W_right f32 [128*128], W_update f32 [128*128],
// b_update f32 [128], next_size (scalar, ignored).
// Output: f32 [600000*128].
// ---------------------------------------------------------------------------
extern "C" void kernel_launch(void* const* d_in, const int* in_sizes, int n_in,
                              void* d_out, int out_size) {
    const float* emb   = (const float*)d_in[0];
    const void*  edges = d_in[1];
    const float* Wl    = (const float*)d_in[2];
    const float* Wr    = (const float*)d_in[3];
    const float* Wu    = (const float*)d_in[4];
    const float* bias  = (const float*)d_in[5];

    int M = in_sizes[0] / PRE;      // nodes
    int E = in_sizes[1] / 2;        // edges
    if (M > MAX_NODES) M = MAX_NODES;

    // dtype detection (first E u64 words are in-bounds for both dtypes)
    reset_flag_kernel<<<1, 1>>>();
    detect_kernel<<<512, 256>>>((const unsigned long long*)edges, E);

    const size_t smem = (size_t)(64 * 132 + 128 * 132) * sizeof(float); // 101376 B
    cudaFuncSetAttribute(node_gemm_kernel,
                         cudaFuncAttributeMaxDynamicSharedMemorySize, (int)smem);

    dim3 g1((M + 63) / 64, 3);
    node_gemm_kernel<<<g1, 256, smem>>>(emb, Wl, Wr, Wu, M);

    long long total_threads = (long long)E * 32;
    int blocks = (int)((total_threads + 255) / 256);
    edge_kernel<<<blocks, 256>>>(edges, bias, (float*)d_out, E, M);
}

// round 17
// speedup vs baseline: 1.0047x; 1.0047x over previous
#include <cuda_runtime.h>
#include <cuda_fp16.h>
#include <cstdint>
#include <math.h>

#define PRE        128
#define NSTRIDE    384          // per-node row in P (halves): [SL(128)|SR(128)|U(128)]
#define MAX_NODES  100000
#define BM         128
#define LDA        136          // smem row stride in halves (conflict-free fragments)

// Scratch: per-node precomputed activations, fp16. 100000*384*2 = 76.8 MB (L2-resident).
static __device__ __align__(16) __half g_P[(size_t)MAX_NODES * NSTRIDE];

// edges-dtype flag: 1 if edges buffer is int32, 0 if int64.
static __device__ int g_is32;

// ---------------------------------------------------------------------------
// Dtype detection: sample the first n64 u64 words (in-bounds for both dtypes).
// int64 indices are all < 100000; int32 pairs fused into u64 are >= 2^32
// unless the high index is 0 (P = 1e-5 per word -> 32768 words never all low).
// ---------------------------------------------------------------------------
__global__ void reset_flag_kernel() { g_is32 = 0; }

__global__ void detect_kernel(const unsigned long long* __restrict__ p, int n64) {
    int i = blockIdx.x * blockDim.x + threadIdx.x;
    bool bad = false;
    for (; i < n64; i += gridDim.x * blockDim.x)
        bad |= (p[i] >= (unsigned long long)MAX_NODES);
    if (bad) g_is32 = 1;
}

// ---------------------------------------------------------------------------
// Kernel 1 (fused): P[n] = [sigmoid(emb@Wl^T) | sigmoid(emb@Wr^T) | emb@Wu^T]
// One block: 128 node rows, ALL 3 weight matrices staged in SMEM (fp16),
// emb read once. 512 threads = 16 warps as 4(M) x 4(N); m16n8k16 fp16 MMA.
// ---------------------------------------------------------------------------
__global__ void node_gemm_kernel(const float* __restrict__ emb,
                                 const float* __restrict__ Wl,
                                 const float* __restrict__ Wr,
                                 const float* __restrict__ Wu,
                                 int M) {
    extern __shared__ __half sh[];
    __half* As = sh;                  // [128][LDA]
    __half* Bs = sh + BM * LDA;       // [3][128][LDA]

    const int tid = threadIdx.x;
    const int m0 = blockIdx.x * BM;

    // Stage A (128x128 emb rows -> fp16): 4096 float4, 8 per thread
#pragma unroll
    for (int i = 0; i < 8; i++) {
        int idx = tid + i * 512;
        int r = idx >> 5;
        int c4 = idx & 31;
        float4 v = make_float4(0.f, 0.f, 0.f, 0.f);
        if (m0 + r < M)
            v = __ldg((const float4*)(emb + (size_t)(m0 + r) * PRE) + c4);
        __half2 h01 = __floats2half2_rn(v.x, v.y);
        __half2 h23 = __floats2half2_rn(v.z, v.w);
        uint2 pk = make_uint2(*(unsigned*)&h01, *(unsigned*)&h23);
        *(uint2*)&As[r * LDA + c4 * 4] = pk;
    }
    // Stage B: 3 weight matrices (128x128 each -> fp16): 8 float4/thread/seg
    const float* Ws[3] = {Wl, Wr, Wu};
#pragma unroll
    for (int s = 0; s < 3; s++) {
        const float* W = Ws[s];
        __half* Bseg = Bs + s * 128 * LDA;
#pragma unroll
        for (int i = 0; i < 8; i++) {
            int idx = tid + i * 512;
            int n = idx >> 5;
            int c4 = idx & 31;
            float4 v = __ldg((const float4*)(W + n * PRE) + c4);
            __half2 h01 = __floats2half2_rn(v.x, v.y);
            __half2 h23 = __floats2half2_rn(v.z, v.w);
            uint2 pk = make_uint2(*(unsigned*)&h01, *(unsigned*)&h23);
            *(uint2*)&Bseg[n * LDA + c4 * 4] = pk;
        }
    }
    __syncthreads();

    const int lane = tid & 31;
    const int wid = tid >> 5;
    const int wm = wid & 3;          // warp row: 32 node-rows each
    const int wn = wid >> 2;         // warp col: 32 out-cols each
    const int g  = lane >> 2;        // groupID 0..7
    const int t4 = lane & 3;         // threadID_in_group 0..3

#pragma unroll
    for (int seg = 0; seg < 3; seg++) {
        const __half* Bseg = Bs + seg * 128 * LDA;
        float acc[2][4][4];
#pragma unroll
        for (int mi = 0; mi < 2; mi++)
#pragma unroll
            for (int ni = 0; ni < 4; ni++)
#pragma unroll
                for (int j = 0; j < 4; j++) acc[mi][ni][j] = 0.f;

#pragma unroll
        for (int ko = 0; ko < 8; ko++) {
            const int k0 = ko * 16 + 2 * t4;
            unsigned a[2][4];
#pragma unroll
            for (int mi = 0; mi < 2; mi++) {
                int r = wm * 32 + mi * 16 + g;
                a[mi][0] = *(const unsigned*)&As[r * LDA + k0];
                a[mi][1] = *(const unsigned*)&As[(r + 8) * LDA + k0];
                a[mi][2] = *(const unsigned*)&As[r * LDA + k0 + 8];
                a[mi][3] = *(const unsigned*)&As[(r + 8) * LDA + k0 + 8];
            }
#pragma unroll
            for (int ni = 0; ni < 4; ni++) {
                int n = wn * 32 + ni * 8 + g;
                unsigned b0 = *(const unsigned*)&Bseg[n * LDA + k0];
                unsigned b1 = *(const unsigned*)&Bseg[n * LDA + k0 + 8];
#pragma unroll
                for (int mi = 0; mi < 2; mi++) {
                    asm volatile(
                        "mma.sync.aligned.m16n8k16.row.col.f32.f16.f16.f32 "
                        "{%0,%1,%2,%3}, {%4,%5,%6,%7}, {%8,%9}, {%0,%1,%2,%3};\n"
                        : "+f"(acc[mi][ni][0]), "+f"(acc[mi][ni][1]),
                          "+f"(acc[mi][ni][2]), "+f"(acc[mi][ni][3])
                        : "r"(a[mi][0]), "r"(a[mi][1]), "r"(a[mi][2]), "r"(a[mi][3]),
                          "r"(b0), "r"(b1));
                }
            }
        }

        // Epilogue: sigmoid for segs 0/1; raw U for seg 2. Store fp16.
#pragma unroll
        for (int mi = 0; mi < 2; mi++) {
#pragma unroll
            for (int ni = 0; ni < 4; ni++) {
                int row = m0 + wm * 32 + mi * 16 + g;
                int col = wn * 32 + ni * 8 + 2 * t4;
                float v0 = acc[mi][ni][0], v1 = acc[mi][ni][1];
                float v2 = acc[mi][ni][2], v3 = acc[mi][ni][3];
                if (seg < 2) {
                    v0 = 1.f / (1.f + expf(-v0));
                    v1 = 1.f / (1.f + expf(-v1));
                    v2 = 1.f / (1.f + expf(-v2));
                    v3 = 1.f / (1.f + expf(-v3));
                }
                if (row < M) {
                    __half2 h = __floats2half2_rn(v0, v1);
                    *(__half2*)&g_P[(size_t)row * NSTRIDE + seg * 128 + col] = h;
                }
                if (row + 8 < M) {
                    __half2 h = __floats2half2_rn(v2, v3);
                    *(__half2*)&g_P[(size_t)(row + 8) * NSTRIDE + seg * 128 + col] = h;
                }
            }
        }
    }
}

// ---------------------------------------------------------------------------
// Kernel 2: per-edge gather + elementwise. 1 warp per edge, lane owns 4 cols.
// out[e] = (SL[a] + SR[b]) * tanh(U[a] + U[b] + bias)
// Output written with __stcs (evict-first) so the fp16 table stays L2-resident.
// ---------------------------------------------------------------------------
__global__ void edge_kernel(const void* __restrict__ edges,
                            const float* __restrict__ bias,
                            float* __restrict__ out,
                            int E, int M) {
    int w = (int)((blockIdx.x * blockDim.x + threadIdx.x) >> 5);
    if (w >= E) return;
    int lane = threadIdx.x & 31;

    int ia, ib;
    if (g_is32) {
        int2 e = __ldg((const int2*)edges + w);
        ia = e.x; ib = e.y;
    } else {
        longlong2 e = __ldg((const longlong2*)edges + w);
        ia = (int)e.x; ib = (int)e.y;
    }
    ia = (ia < 0) ? 0 : (ia >= M ? M - 1 : ia);
    ib = (ib < 0) ? 0 : (ib >= M ? M - 1 : ib);

    const __half* Pa = g_P + (unsigned)ia * NSTRIDE;   // 32-bit address math
    const __half* Pb = g_P + (unsigned)ib * NSTRIDE;
    const int c = lane << 2;                           // 4 halves per lane

    uint2 sl = *(const uint2*)(Pa + c);                // SL[a]
    uint2 sr = *(const uint2*)(Pb + 128 + c);          // SR[b]
    uint2 ua = *(const uint2*)(Pa + 256 + c);          // U[a]
    uint2 ub = *(const uint2*)(Pb + 256 + c);          // U[b]
    float4 bv = __ldg((const float4*)bias + lane);

    float2 sl0 = __half22float2(*(__half2*)&sl.x), sl1 = __half22float2(*(__half2*)&sl.y);
    float2 sr0 = __half22float2(*(__half2*)&sr.x), sr1 = __half22float2(*(__half2*)&sr.y);
    float2 ua0 = __half22float2(*(__half2*)&ua.x), ua1 = __half22float2(*(__half2*)&ua.y);
    float2 ub0 = __half22float2(*(__half2*)&ub.x), ub1 = __half22float2(*(__half2*)&ub.y);

    float4 o;
    o.x = (sl0.x + sr0.x) * tanhf(ua0.x + ub0.x + bv.x);
    o.y = (sl0.y + sr0.y) * tanhf(ua0.y + ub0.y + bv.y);
    o.z = (sl1.x + sr1.x) * tanhf(ua1.x + ub1.x + bv.z);
    o.w = (sl1.y + sr1.y) * tanhf(ua1.y + ub1.y + bv.w);

    __stcs((float4*)out + (unsigned)w * 32u + lane, o);
}

// ---------------------------------------------------------------------------
// Inputs: node_embedding f32 [100000*128], edges i32/i64 [600000*2] (detected),
// W_left/W_right/W_update f32 [128*128], b_update f32 [128], next_size (ignored).
// Output: f32 [600000*128].
// ---------------------------------------------------------------------------
extern "C" void kernel_launch(void* const* d_in, const int* in_sizes, int n_in,
                              void* d_out, int out_size) {
    const float* emb   = (const float*)d_in[0];
    const void*  edges = d_in[1];
    const float* Wl    = (const float*)d_in[2];
    const float* Wr    = (const float*)d_in[3];
    const float* Wu    = (const float*)d_in[4];
    const float* bias  = (const float*)d_in[5];

    int M = in_sizes[0] / PRE;      // nodes
    int E = in_sizes[1] / 2;        // edges
    if (M > MAX_NODES) M = MAX_NODES;

    // dtype detection over a 256 KB sample (in-bounds for both dtypes)
    int nDet = (E < 32768) ? E : 32768;
    reset_flag_kernel<<<1, 1>>>();
    detect_kernel<<<32, 256>>>((const unsigned long long*)edges, nDet);

    const size_t smem = (size_t)(4 * BM * LDA) * sizeof(__half); // 139264 B
    cudaFuncSetAttribute(node_gemm_kernel,
                         cudaFuncAttributeMaxDynamicSharedMemorySize, (int)smem);

    node_gemm_kernel<<<(M + BM - 1) / BM, 512, smem>>>(emb, Wl, Wr, Wu, M);

    long long total_threads = (long long)E * 32;
    int blocks = (int)((total_threads + 255) / 256);
    edge_kernel<<<blocks, 256>>>(edges, bias, (float*)d_out, E, M);
}